// round 2
// baseline (speedup 1.0000x reference)
#include <cuda_runtime.h>

#define NNODES 200000
#define NEDGES 100000
#define NNZV   2000000
#define HID    64

// ---------------- scratch (static device allocations) ----------------
__device__ __align__(128) float g_z[(size_t)NNODES * HID];      // node accumulator (51.2 MB)
__device__ __align__(128) float g_eraw[(size_t)NEDGES * HID];   // edge raw sums (25.6 MB)
__device__ __align__(128) float g_efeat[(size_t)NEDGES * HID];  // transformed edge feats (25.6 MB)
__device__ float g_Dsum[NNODES];
__device__ float g_Dinv[NNODES];
__device__ float g_Bcnt[NEDGES];
__device__ float g_c2[NEDGES];   // ew * Binv
__device__ float g_cb[NEDGES];   // ew * Binv * B  (bias coefficient)

__device__ __forceinline__ void red_add_v4(float* addr, float4 v) {
    asm volatile("red.global.add.v4.f32 [%0], {%1,%2,%3,%4};"
                 :: "l"(addr), "f"(v.x), "f"(v.y), "f"(v.z), "f"(v.w)
                 : "memory");
}

// ---------------- degree precompute ----------------
__global__ void deg_zero_kernel() {
    int i = blockIdx.x * blockDim.x + threadIdx.x;
    if (i < NNODES) g_Dsum[i] = 0.f;
    if (i < NEDGES) g_Bcnt[i] = 0.f;
}

__global__ void deg_scatter_kernel(const int* __restrict__ nidx,
                                   const int* __restrict__ eidx,
                                   const float* __restrict__ ew) {
    int i = blockIdx.x * blockDim.x + threadIdx.x;
    if (i >= NNZV) return;
    int v = nidx[i];
    int e = eidx[i];
    atomicAdd(&g_Dsum[v], __ldg(&ew[e]));
    atomicAdd(&g_Bcnt[e], 1.0f);
}

__global__ void deg_final_kernel(const float* __restrict__ ew) {
    int i = blockIdx.x * blockDim.x + threadIdx.x;
    if (i < NNODES) {
        float d = g_Dsum[i];
        g_Dinv[i] = (d > 0.f) ? (1.f / d) : 0.f;
    }
    if (i < NEDGES) {
        float b  = g_Bcnt[i];
        float bi = (b > 0.f) ? (1.f / b) : 0.f;
        float w  = ew[i];
        g_c2[i] = w * bi;
        g_cb[i] = w * bi * b;
    }
}

// ---------------- zeroing ----------------
__global__ void zero_eraw_kernel() {
    int i = blockIdx.x * blockDim.x + threadIdx.x;
    if (i < NEDGES * (HID / 4)) reinterpret_cast<float4*>(g_eraw)[i] = make_float4(0.f, 0.f, 0.f, 0.f);
}
__global__ void zero_z_kernel() {
    int i = blockIdx.x * blockDim.x + threadIdx.x;
    if (i < NNODES * (HID / 4)) reinterpret_cast<float4*>(g_z)[i] = make_float4(0.f, 0.f, 0.f, 0.f);
}

// ---------------- scatter node -> edge ----------------
// 16 lanes per nnz, each lane handles one float4 of the 64-wide row.
// Indices loaded once per 16-lane group (lane 0) and broadcast via shfl.
// MODE 0: x = external input (emb).  MODE 1: x = relu(Dinv * g_z).
template <int MODE>
__global__ __launch_bounds__(256) void scatter_v2e_kernel(const int* __restrict__ nidx,
                                                          const int* __restrict__ eidx,
                                                          const float* __restrict__ x) {
    int t = blockIdx.x * blockDim.x + threadIdx.x;
    int nnz = t >> 4;
    if (nnz >= NNZV) return;
    int lane = threadIdx.x & 31;
    int sub  = lane & 15;            // lane within 16-group
    int v, e;
    if (sub == 0) { v = nidx[nnz]; e = eidx[nnz]; }
    v = __shfl_sync(0xFFFFFFFFu, v, lane & 16);
    e = __shfl_sync(0xFFFFFFFFu, e, lane & 16);
    int c = sub * 4;
    float4 x4;
    if (MODE == 0) {
        x4 = *reinterpret_cast<const float4*>(x + (size_t)v * HID + c);
    } else {
        x4 = *reinterpret_cast<const float4*>(g_z + (size_t)v * HID + c);
        float s = __ldg(&g_Dinv[v]);
        x4.x = fmaxf(x4.x * s, 0.f);
        x4.y = fmaxf(x4.y * s, 0.f);
        x4.z = fmaxf(x4.z * s, 0.f);
        x4.w = fmaxf(x4.w * s, 0.f);
    }
    red_add_v4(g_eraw + (size_t)e * HID + c, x4);
}

// ---------------- scatter edge -> node ----------------
__global__ __launch_bounds__(256) void scatter_e2v_kernel(const int* __restrict__ nidx,
                                                          const int* __restrict__ eidx) {
    int t = blockIdx.x * blockDim.x + threadIdx.x;
    int nnz = t >> 4;
    if (nnz >= NNZV) return;
    int lane = threadIdx.x & 31;
    int sub  = lane & 15;
    int v, e;
    if (sub == 0) { v = nidx[nnz]; e = eidx[nnz]; }
    v = __shfl_sync(0xFFFFFFFFu, v, lane & 16);
    e = __shfl_sync(0xFFFFFFFFu, e, lane & 16);
    int c = sub * 4;
    float4 f = *reinterpret_cast<const float4*>(g_efeat + (size_t)e * HID + c);
    red_add_v4(g_z + (size_t)v * HID + c, f);
}

// ---------------- edge GEMM: efeat[e,:] = c2[e]*(eraw[e,:] @ W^T) + cb[e]*b ----------------
// 256 threads, 128 rows/block. Thread (rp = tid>>2 handles rows 2rp,2rp+1; cq = tid&3
// handles 16 interleaved output cols j in {cq*4 + jq*16 + 0..3}).
__global__ __launch_bounds__(256) void edge_gemm_kernel(const float* __restrict__ W,
                                                        const float* __restrict__ b) {
    __shared__ float WsT[HID][HID];  // WsT[k][j] = W[j,k]
    __shared__ float bs[HID];

    int tid = threadIdx.x;
    // load W transposed: conflict-free STS, strided LDG (tiny, L1-absorbed)
    for (int idx = tid; idx < HID * HID; idx += 256) {
        int j = idx & (HID - 1);
        int k = idx >> 6;
        WsT[k][j] = W[j * HID + k];
    }
    if (tid < HID) bs[tid] = b[tid];
    __syncthreads();

    int rp = tid >> 2;
    int cq = tid & 3;
    int r0 = blockIdx.x * 128 + rp * 2;
    int r1 = r0 + 1;
    bool ok0 = (r0 < NEDGES);
    bool ok1 = (r1 < NEDGES);

    float4 a0[4], a1[4];
#pragma unroll
    for (int jq = 0; jq < 4; jq++) {
        a0[jq] = make_float4(0.f, 0.f, 0.f, 0.f);
        a1[jq] = make_float4(0.f, 0.f, 0.f, 0.f);
    }

    const float4* x0p = reinterpret_cast<const float4*>(g_eraw + (size_t)(ok0 ? r0 : 0) * HID);
    const float4* x1p = reinterpret_cast<const float4*>(g_eraw + (size_t)(ok1 ? r1 : 0) * HID);

#pragma unroll 4
    for (int k4 = 0; k4 < HID / 4; k4++) {
        float4 xa = ok0 ? __ldg(&x0p[k4]) : make_float4(0.f, 0.f, 0.f, 0.f);
        float4 xb = ok1 ? __ldg(&x1p[k4]) : make_float4(0.f, 0.f, 0.f, 0.f);
        float xav[4] = {xa.x, xa.y, xa.z, xa.w};
        float xbv[4] = {xb.x, xb.y, xb.z, xb.w};
#pragma unroll
        for (int kk = 0; kk < 4; kk++) {
            int k = k4 * 4 + kk;
#pragma unroll
            for (int jq = 0; jq < 4; jq++) {
                float4 w = *reinterpret_cast<const float4*>(&WsT[k][cq * 4 + jq * 16]);
                a0[jq].x = fmaf(xav[kk], w.x, a0[jq].x);
                a0[jq].y = fmaf(xav[kk], w.y, a0[jq].y);
                a0[jq].z = fmaf(xav[kk], w.z, a0[jq].z);
                a0[jq].w = fmaf(xav[kk], w.w, a0[jq].w);
                a1[jq].x = fmaf(xbv[kk], w.x, a1[jq].x);
                a1[jq].y = fmaf(xbv[kk], w.y, a1[jq].y);
                a1[jq].z = fmaf(xbv[kk], w.z, a1[jq].z);
                a1[jq].w = fmaf(xbv[kk], w.w, a1[jq].w);
            }
        }
    }

    if (ok0) {
        float c2 = g_c2[r0];
        float cb = g_cb[r0];
#pragma unroll
        for (int jq = 0; jq < 4; jq++) {
            int jb = jq * 16 + cq * 4;
            float4 r;
            r.x = fmaf(cb, bs[jb + 0], c2 * a0[jq].x);
            r.y = fmaf(cb, bs[jb + 1], c2 * a0[jq].y);
            r.z = fmaf(cb, bs[jb + 2], c2 * a0[jq].z);
            r.w = fmaf(cb, bs[jb + 3], c2 * a0[jq].w);
            *reinterpret_cast<float4*>(g_efeat + (size_t)r0 * HID + jb) = r;
        }
    }
    if (ok1) {
        float c2 = g_c2[r1];
        float cb = g_cb[r1];
#pragma unroll
        for (int jq = 0; jq < 4; jq++) {
            int jb = jq * 16 + cq * 4;
            float4 r;
            r.x = fmaf(cb, bs[jb + 0], c2 * a1[jq].x);
            r.y = fmaf(cb, bs[jb + 1], c2 * a1[jq].y);
            r.z = fmaf(cb, bs[jb + 2], c2 * a1[jq].z);
            r.w = fmaf(cb, bs[jb + 3], c2 * a1[jq].w);
            *reinterpret_cast<float4*>(g_efeat + (size_t)r1 * HID + jb) = r;
        }
    }
}

// ---------------- final: out = Dinv * z (no relu on last layer) ----------------
__global__ void finalize_kernel(float* __restrict__ out) {
    int t = blockIdx.x * blockDim.x + threadIdx.x;
    if (t >= NNODES * (HID / 4)) return;
    int v = t >> 4;
    float s = g_Dinv[v];
    float4 z = reinterpret_cast<const float4*>(g_z)[t];
    z.x *= s; z.y *= s; z.z *= s; z.w *= s;
    reinterpret_cast<float4*>(out)[t] = z;
}

// ---------------- launch ----------------
extern "C" void kernel_launch(void* const* d_in, const int* in_sizes, int n_in,
                              void* d_out, int out_size) {
    const int*   hidx = (const int*)d_in[0];
    const int*   nidx = hidx;             // hyperedge_index[0] = node idx
    const int*   eidx = hidx + NNZV;      // hyperedge_index[1] = edge idx
    const float* ew   = (const float*)d_in[1];
    const float* emb  = (const float*)d_in[2];
    const float* Wm[3] = {(const float*)d_in[3], (const float*)d_in[5], (const float*)d_in[7]};
    const float* bm[3] = {(const float*)d_in[4], (const float*)d_in[6], (const float*)d_in[8]};
    float* out = (float*)d_out;

    const int T = 256;
    // degrees (layer-invariant)
    deg_zero_kernel<<<(NNODES + T - 1) / T, T>>>();
    deg_scatter_kernel<<<(NNZV + T - 1) / T, T>>>(nidx, eidx, ew);
    deg_final_kernel<<<(NNODES + T - 1) / T, T>>>(ew);

    const int SCAT_BLOCKS = (NNZV * 16) / T;            // 125000
    const int ZE_BLOCKS   = (NEDGES * (HID / 4) + T - 1) / T;
    const int ZN_BLOCKS   = (NNODES * (HID / 4) + T - 1) / T;
    const int GEMM_BLOCKS = (NEDGES + 127) / 128;       // 782

    for (int l = 0; l < 3; l++) {
        zero_eraw_kernel<<<ZE_BLOCKS, T>>>();
        if (l == 0)
            scatter_v2e_kernel<0><<<SCAT_BLOCKS, T>>>(nidx, eidx, emb);
        else
            scatter_v2e_kernel<1><<<SCAT_BLOCKS, T>>>(nidx, eidx, nullptr);
        edge_gemm_kernel<<<GEMM_BLOCKS, T>>>(Wm[l], bm[l]);
        zero_z_kernel<<<ZN_BLOCKS, T>>>();
        scatter_e2v_kernel<<<SCAT_BLOCKS, T>>>(nidx, eidx);
    }
    finalize_kernel<<<(NNODES * (HID / 4) + T - 1) / T, T>>>(out);
}

// round 4
// speedup vs baseline: 2.0199x; 2.0199x over previous
#include <cuda_runtime.h>

#define NNODES 200000
#define NEDGES 100000
#define NNZV   2000000
#define HID    64

// ---------------- scratch (static device allocations) ----------------
__device__ __align__(128) float g_z[(size_t)NNODES * HID];      // node features (51.2 MB)
__device__ __align__(128) float g_eraw[(size_t)NEDGES * HID];   // edge raw sums (25.6 MB)
__device__ __align__(128) float g_efeat[(size_t)NEDGES * HID];  // transformed edge feats (25.6 MB)
__device__ float g_Dsum[NNODES];
__device__ float g_Dinv[NNODES];
__device__ float g_c2[NEDGES];   // ew * Binv
__device__ float g_cb[NEDGES];   // ew (bias coeff, 0 if empty edge)
__device__ int   g_degE[NEDGES];
__device__ int   g_degV[NNODES];
__device__ int   g_offE[NEDGES + 1];
__device__ int   g_offV[NNODES + 1];
__device__ int   g_curE[NEDGES];
__device__ int   g_curV[NNODES];
__device__ int   g_csrE[NNZV];   // node ids grouped by edge
__device__ int   g_csrV[NNZV];   // edge ids grouped by node
__device__ int   g_bsumE[256];   // scan block sums (100K/1024 = 98)
__device__ int   g_bsumV[256];   // 200K/1024 = 196

// selectors so host never needs device-symbol addresses
__device__ __forceinline__ int* sel_deg(int w)  { return w ? g_degV  : g_degE; }
__device__ __forceinline__ int* sel_off(int w)  { return w ? g_offV  : g_offE; }
__device__ __forceinline__ int* sel_cur(int w)  { return w ? g_curV  : g_curE; }
__device__ __forceinline__ int* sel_bsum(int w) { return w ? g_bsumV : g_bsumE; }
__device__ __forceinline__ int  sel_n(int w)    { return w ? NNODES  : NEDGES; }

// ---------------- degree / coefficient precompute ----------------
__global__ void deg_zero_kernel() {
    int i = blockIdx.x * blockDim.x + threadIdx.x;
    if (i < NNODES) { g_Dsum[i] = 0.f; g_degV[i] = 0; }
    if (i < NEDGES) { g_degE[i] = 0; }
}

__global__ void deg_count_kernel(const int* __restrict__ nidx,
                                 const int* __restrict__ eidx,
                                 const float* __restrict__ ew) {
    int i = blockIdx.x * blockDim.x + threadIdx.x;
    if (i >= NNZV) return;
    int v = nidx[i];
    int e = eidx[i];
    atomicAdd(&g_degE[e], 1);
    atomicAdd(&g_degV[v], 1);
    atomicAdd(&g_Dsum[v], __ldg(&ew[e]));
}

__global__ void deg_final_kernel(const float* __restrict__ ew) {
    int i = blockIdx.x * blockDim.x + threadIdx.x;
    if (i < NNODES) {
        float d = g_Dsum[i];
        g_Dinv[i] = (d > 0.f) ? (1.f / d) : 0.f;
    }
    if (i < NEDGES) {
        float B = (float)g_degE[i];
        float w = ew[i];
        if (B > 0.f) { g_c2[i] = w / B; g_cb[i] = w; }
        else         { g_c2[i] = 0.f;   g_cb[i] = 0.f; }
    }
}

// ---------------- 3-kernel exclusive scan over degree arrays ----------------
__global__ __launch_bounds__(256) void scan1_kernel(int w) {
    int n = sel_n(w);
    const int* deg = sel_deg(w);
    int t = threadIdx.x;
    int base = blockIdx.x * 1024 + t * 4;
    int s = 0;
#pragma unroll
    for (int k = 0; k < 4; k++) {
        int i = base + k;
        if (i < n) s += deg[i];
    }
    __shared__ int sh[256];
    sh[t] = s;
    __syncthreads();
    for (int o = 128; o > 0; o >>= 1) {
        if (t < o) sh[t] += sh[t + o];
        __syncthreads();
    }
    if (t == 0) sel_bsum(w)[blockIdx.x] = sh[0];
}

__global__ __launch_bounds__(256) void scan2_kernel(int w) {
    int nb = (sel_n(w) + 1023) / 1024;
    int t = threadIdx.x;
    int v = (t < nb) ? sel_bsum(w)[t] : 0;
    __shared__ int sh[256];
    sh[t] = v;
    __syncthreads();
    for (int o = 1; o < 256; o <<= 1) {
        int x = (t >= o) ? sh[t - o] : 0;
        __syncthreads();
        sh[t] += x;
        __syncthreads();
    }
    if (t < nb) sel_bsum(w)[t] = sh[t] - v;   // exclusive
    if (t == 0) sel_off(w)[sel_n(w)] = NNZV;
}

__global__ __launch_bounds__(256) void scan3_kernel(int w) {
    int n = sel_n(w);
    const int* deg = sel_deg(w);
    int* off = sel_off(w);
    int* cur = sel_cur(w);
    int t = threadIdx.x;
    int base = blockIdx.x * 1024 + t * 4;
    int a[4];
    int s = 0;
#pragma unroll
    for (int k = 0; k < 4; k++) {
        int i = base + k;
        a[k] = (i < n) ? deg[i] : 0;
        s += a[k];
    }
    __shared__ int sh[256];
    sh[t] = s;
    __syncthreads();
    for (int o = 1; o < 256; o <<= 1) {
        int x = (t >= o) ? sh[t - o] : 0;
        __syncthreads();
        sh[t] += x;
        __syncthreads();
    }
    int run = sh[t] - s + sel_bsum(w)[blockIdx.x];
#pragma unroll
    for (int k = 0; k < 4; k++) {
        int i = base + k;
        if (i < n) {
            off[i] = run;
            cur[i] = run;
            run += a[k];
        }
    }
}

// fill both CSRs via cursor atomics
__global__ void fill_csr_kernel(const int* __restrict__ nidx,
                                const int* __restrict__ eidx) {
    int i = blockIdx.x * blockDim.x + threadIdx.x;
    if (i >= NNZV) return;
    int v = nidx[i];
    int e = eidx[i];
    int pe = atomicAdd(&g_curE[e], 1);
    g_csrE[pe] = v;
    int pv = atomicAdd(&g_curV[v], 1);
    g_csrV[pv] = e;
}

// ---------------- gather node -> edge ----------------
// 16 lanes per edge row, each lane owns one float4 column chunk.
// Software-pipelined by 4: batch idx loads, issue 4 independent row loads.
// MODE 0: x = emb.  MODE 1: x = relu(g_z)  (g_z already has Dinv folded).
template <int MODE>
__global__ __launch_bounds__(256) void gather_v2e_kernel(const float* __restrict__ x) {
    int t = blockIdx.x * 256 + threadIdx.x;
    int e = t >> 4;
    if (e >= NEDGES) return;
    int c = (t & 15) * 4;
    int start = __ldg(&g_offE[e]);
    int end   = __ldg(&g_offE[e + 1]);
    const float* src = (MODE == 0) ? x : g_z;

    float4 acc = make_float4(0.f, 0.f, 0.f, 0.f);
    int j = start;
    for (; j + 3 < end; j += 4) {
        int v0 = __ldg(&g_csrE[j]);
        int v1 = __ldg(&g_csrE[j + 1]);
        int v2 = __ldg(&g_csrE[j + 2]);
        int v3 = __ldg(&g_csrE[j + 3]);
        float4 a = *reinterpret_cast<const float4*>(src + (size_t)v0 * HID + c);
        float4 b = *reinterpret_cast<const float4*>(src + (size_t)v1 * HID + c);
        float4 d = *reinterpret_cast<const float4*>(src + (size_t)v2 * HID + c);
        float4 f = *reinterpret_cast<const float4*>(src + (size_t)v3 * HID + c);
        if (MODE == 1) {
            a.x = fmaxf(a.x, 0.f); a.y = fmaxf(a.y, 0.f); a.z = fmaxf(a.z, 0.f); a.w = fmaxf(a.w, 0.f);
            b.x = fmaxf(b.x, 0.f); b.y = fmaxf(b.y, 0.f); b.z = fmaxf(b.z, 0.f); b.w = fmaxf(b.w, 0.f);
            d.x = fmaxf(d.x, 0.f); d.y = fmaxf(d.y, 0.f); d.z = fmaxf(d.z, 0.f); d.w = fmaxf(d.w, 0.f);
            f.x = fmaxf(f.x, 0.f); f.y = fmaxf(f.y, 0.f); f.z = fmaxf(f.z, 0.f); f.w = fmaxf(f.w, 0.f);
        }
        acc.x += (a.x + b.x) + (d.x + f.x);
        acc.y += (a.y + b.y) + (d.y + f.y);
        acc.z += (a.z + b.z) + (d.z + f.z);
        acc.w += (a.w + b.w) + (d.w + f.w);
    }
    for (; j < end; j++) {
        int v0 = __ldg(&g_csrE[j]);
        float4 a = *reinterpret_cast<const float4*>(src + (size_t)v0 * HID + c);
        if (MODE == 1) {
            a.x = fmaxf(a.x, 0.f); a.y = fmaxf(a.y, 0.f); a.z = fmaxf(a.z, 0.f); a.w = fmaxf(a.w, 0.f);
        }
        acc.x += a.x; acc.y += a.y; acc.z += a.z; acc.w += a.w;
    }
    *reinterpret_cast<float4*>(g_eraw + (size_t)e * HID + c) = acc;
}

// ---------------- gather edge -> node ----------------
// efeat already includes ew*Binv; just sum and scale by Dinv.
// LAST=0: write g_z.  LAST=1: write out.
template <int LAST>
__global__ __launch_bounds__(256) void gather_e2v_kernel(float* __restrict__ out) {
    int t = blockIdx.x * 256 + threadIdx.x;
    int v = t >> 4;
    if (v >= NNODES) return;
    int c = (t & 15) * 4;
    int start = __ldg(&g_offV[v]);
    int end   = __ldg(&g_offV[v + 1]);

    float4 acc = make_float4(0.f, 0.f, 0.f, 0.f);
    int j = start;
    for (; j + 3 < end; j += 4) {
        int e0 = __ldg(&g_csrV[j]);
        int e1 = __ldg(&g_csrV[j + 1]);
        int e2 = __ldg(&g_csrV[j + 2]);
        int e3 = __ldg(&g_csrV[j + 3]);
        float4 a = *reinterpret_cast<const float4*>(g_efeat + (size_t)e0 * HID + c);
        float4 b = *reinterpret_cast<const float4*>(g_efeat + (size_t)e1 * HID + c);
        float4 d = *reinterpret_cast<const float4*>(g_efeat + (size_t)e2 * HID + c);
        float4 f = *reinterpret_cast<const float4*>(g_efeat + (size_t)e3 * HID + c);
        acc.x += (a.x + b.x) + (d.x + f.x);
        acc.y += (a.y + b.y) + (d.y + f.y);
        acc.z += (a.z + b.z) + (d.z + f.z);
        acc.w += (a.w + b.w) + (d.w + f.w);
    }
    for (; j < end; j++) {
        int e0 = __ldg(&g_csrV[j]);
        float4 a = *reinterpret_cast<const float4*>(g_efeat + (size_t)e0 * HID + c);
        acc.x += a.x; acc.y += a.y; acc.z += a.z; acc.w += a.w;
    }
    float s = __ldg(&g_Dinv[v]);
    acc.x *= s; acc.y *= s; acc.z *= s; acc.w *= s;
    float* dst = LAST ? out : g_z;
    *reinterpret_cast<float4*>(dst + (size_t)v * HID + c) = acc;
}

// ---------------- edge GEMM: efeat[e,:] = c2[e]*(eraw[e,:] @ W^T) + cb[e]*b ----------------
__global__ __launch_bounds__(256) void edge_gemm_kernel(const float* __restrict__ W,
                                                        const float* __restrict__ b) {
    __shared__ float WsT[HID][HID];  // WsT[k][j] = W[j,k]
    __shared__ float bs[HID];

    int tid = threadIdx.x;
    for (int idx = tid; idx < HID * HID; idx += 256) {
        int j = idx & (HID - 1);
        int k = idx >> 6;
        WsT[k][j] = W[j * HID + k];
    }
    if (tid < HID) bs[tid] = b[tid];
    __syncthreads();

    int rp = tid >> 2;
    int cq = tid & 3;
    int r0 = blockIdx.x * 128 + rp * 2;
    int r1 = r0 + 1;
    bool ok0 = (r0 < NEDGES);
    bool ok1 = (r1 < NEDGES);

    float4 a0[4], a1[4];
#pragma unroll
    for (int jq = 0; jq < 4; jq++) {
        a0[jq] = make_float4(0.f, 0.f, 0.f, 0.f);
        a1[jq] = make_float4(0.f, 0.f, 0.f, 0.f);
    }

    const float4* x0p = reinterpret_cast<const float4*>(g_eraw + (size_t)(ok0 ? r0 : 0) * HID);
    const float4* x1p = reinterpret_cast<const float4*>(g_eraw + (size_t)(ok1 ? r1 : 0) * HID);

#pragma unroll 4
    for (int k4 = 0; k4 < HID / 4; k4++) {
        float4 xa = ok0 ? __ldg(&x0p[k4]) : make_float4(0.f, 0.f, 0.f, 0.f);
        float4 xb = ok1 ? __ldg(&x1p[k4]) : make_float4(0.f, 0.f, 0.f, 0.f);
        float xav[4] = {xa.x, xa.y, xa.z, xa.w};
        float xbv[4] = {xb.x, xb.y, xb.z, xb.w};
#pragma unroll
        for (int kk = 0; kk < 4; kk++) {
            int k = k4 * 4 + kk;
#pragma unroll
            for (int jq = 0; jq < 4; jq++) {
                float4 w = *reinterpret_cast<const float4*>(&WsT[k][cq * 4 + jq * 16]);
                a0[jq].x = fmaf(xav[kk], w.x, a0[jq].x);
                a0[jq].y = fmaf(xav[kk], w.y, a0[jq].y);
                a0[jq].z = fmaf(xav[kk], w.z, a0[jq].z);
                a0[jq].w = fmaf(xav[kk], w.w, a0[jq].w);
                a1[jq].x = fmaf(xbv[kk], w.x, a1[jq].x);
                a1[jq].y = fmaf(xbv[kk], w.y, a1[jq].y);
                a1[jq].z = fmaf(xbv[kk], w.z, a1[jq].z);
                a1[jq].w = fmaf(xbv[kk], w.w, a1[jq].w);
            }
        }
    }

    if (ok0) {
        float c2 = g_c2[r0];
        float cb = g_cb[r0];
#pragma unroll
        for (int jq = 0; jq < 4; jq++) {
            int jb = jq * 16 + cq * 4;
            float4 r;
            r.x = fmaf(cb, bs[jb + 0], c2 * a0[jq].x);
            r.y = fmaf(cb, bs[jb + 1], c2 * a0[jq].y);
            r.z = fmaf(cb, bs[jb + 2], c2 * a0[jq].z);
            r.w = fmaf(cb, bs[jb + 3], c2 * a0[jq].w);
            *reinterpret_cast<float4*>(g_efeat + (size_t)r0 * HID + jb) = r;
        }
    }
    if (ok1) {
        float c2 = g_c2[r1];
        float cb = g_cb[r1];
#pragma unroll
        for (int jq = 0; jq < 4; jq++) {
            int jb = jq * 16 + cq * 4;
            float4 r;
            r.x = fmaf(cb, bs[jb + 0], c2 * a1[jq].x);
            r.y = fmaf(cb, bs[jb + 1], c2 * a1[jq].y);
            r.z = fmaf(cb, bs[jb + 2], c2 * a1[jq].z);
            r.w = fmaf(cb, bs[jb + 3], c2 * a1[jq].w);
            *reinterpret_cast<float4*>(g_efeat + (size_t)r1 * HID + jb) = r;
        }
    }
}

// ---------------- launch ----------------
extern "C" void kernel_launch(void* const* d_in, const int* in_sizes, int n_in,
                              void* d_out, int out_size) {
    const int*   hidx = (const int*)d_in[0];
    const int*   nidx = hidx;             // hyperedge_index[0] = node idx
    const int*   eidx = hidx + NNZV;      // hyperedge_index[1] = edge idx
    const float* ew   = (const float*)d_in[1];
    const float* emb  = (const float*)d_in[2];
    const float* Wm[3] = {(const float*)d_in[3], (const float*)d_in[5], (const float*)d_in[7]};
    const float* bm[3] = {(const float*)d_in[4], (const float*)d_in[6], (const float*)d_in[8]};
    float* out = (float*)d_out;

    const int T = 256;
    const int NB_E = (NEDGES + 1023) / 1024;   // 98
    const int NB_V = (NNODES + 1023) / 1024;   // 196

    // degrees + CSR build (layer-invariant)
    deg_zero_kernel<<<(NNODES + T - 1) / T, T>>>();
    deg_count_kernel<<<(NNZV + T - 1) / T, T>>>(nidx, eidx, ew);
    deg_final_kernel<<<(NNODES + T - 1) / T, T>>>(ew);
    scan1_kernel<<<NB_E, T>>>(0);
    scan2_kernel<<<1, T>>>(0);
    scan3_kernel<<<NB_E, T>>>(0);
    scan1_kernel<<<NB_V, T>>>(1);
    scan2_kernel<<<1, T>>>(1);
    scan3_kernel<<<NB_V, T>>>(1);
    fill_csr_kernel<<<(NNZV + T - 1) / T, T>>>(nidx, eidx);

    const int V2E_BLOCKS  = (NEDGES * 16) / T;   // 6250
    const int E2V_BLOCKS  = (NNODES * 16) / T;   // 12500
    const int GEMM_BLOCKS = (NEDGES + 127) / 128;

    for (int l = 0; l < 3; l++) {
        if (l == 0)
            gather_v2e_kernel<0><<<V2E_BLOCKS, T>>>(emb);
        else
            gather_v2e_kernel<1><<<V2E_BLOCKS, T>>>(nullptr);
        edge_gemm_kernel<<<GEMM_BLOCKS, T>>>(Wm[l], bm[l]);
        if (l < 2)
            gather_e2v_kernel<0><<<E2V_BLOCKS, T>>>(nullptr);
        else
            gather_e2v_kernel<1><<<E2V_BLOCKS, T>>>(out);
    }
}

// round 5
// speedup vs baseline: 2.0861x; 1.0328x over previous
#include <cuda_runtime.h>

#define NNODES 200000
#define NEDGES 100000
#define NNZV   2000000
#define HID    64

#define NB_E ((NEDGES + 1023) / 1024)   // 98
#define NB_V ((NNODES + 1023) / 1024)   // 196

// ---------------- scratch (static device allocations; zero-initialized at load) ----------------
__device__ __align__(128) float g_z[(size_t)NNODES * HID];      // node features (51.2 MB)
__device__ __align__(128) float g_eraw[(size_t)NEDGES * HID];   // edge raw sums (25.6 MB)
__device__ __align__(128) float g_efeat[(size_t)NEDGES * HID];  // transformed edge feats (25.6 MB)
__device__ float g_Dsum[NNODES];   // zeroed by trailing cleanup (invariant across graph replays)
__device__ float g_Dinv[NNODES];
__device__ float g_c2[NEDGES];   // ew * Binv
__device__ float g_cb[NEDGES];   // ew (bias coeff, 0 if empty edge)
__device__ int   g_degE[NEDGES]; // zeroed by trailing cleanup
__device__ int   g_degV[NNODES]; // zeroed by trailing cleanup
__device__ int   g_offE[NEDGES + 1];
__device__ int   g_offV[NNODES + 1];
__device__ int   g_curE[NEDGES];
__device__ int   g_curV[NNODES];
__device__ int   g_csrE[NNZV];   // node ids grouped by edge
__device__ int   g_csrV[NNZV];   // edge ids grouped by node
__device__ int   g_bsumE[256];
__device__ int   g_bsumV[256];

// ---------------- launch 1: degree count ----------------
__global__ void deg_count_kernel(const int* __restrict__ nidx,
                                 const int* __restrict__ eidx,
                                 const float* __restrict__ ew) {
    int i = blockIdx.x * blockDim.x + threadIdx.x;
    if (i >= NNZV) return;
    int v = nidx[i];
    int e = eidx[i];
    atomicAdd(&g_degE[e], 1);
    atomicAdd(&g_degV[v], 1);
    atomicAdd(&g_Dsum[v], __ldg(&ew[e]));
}

// ---------------- launch 2: per-block totals for BOTH scans ----------------
__global__ __launch_bounds__(256) void scan1c_kernel() {
    int w   = (blockIdx.x < NB_E) ? 0 : 1;
    int blk = w ? (blockIdx.x - NB_E) : blockIdx.x;
    int n   = w ? NNODES : NEDGES;
    const int* deg = w ? g_degV : g_degE;
    int* bsum = w ? g_bsumV : g_bsumE;

    int t = threadIdx.x;
    int base = blk * 1024 + t * 4;
    int s = 0;
#pragma unroll
    for (int k = 0; k < 4; k++) {
        int i = base + k;
        if (i < n) s += deg[i];
    }
    __shared__ int sh[256];
    sh[t] = s;
    __syncthreads();
    for (int o = 128; o > 0; o >>= 1) {
        if (t < o) sh[t] += sh[t + o];
        __syncthreads();
    }
    if (t == 0) bsum[blk] = sh[0];
}

// ---------------- launch 3: single-block exclusive scan of both block-sum arrays ----------------
__global__ __launch_bounds__(256) void scan2c_kernel() {
    __shared__ int sh[256];
    int t = threadIdx.x;
#pragma unroll
    for (int w = 0; w < 2; w++) {
        int nb = w ? NB_V : NB_E;
        int* bsum = w ? g_bsumV : g_bsumE;
        int v = (t < nb) ? bsum[t] : 0;
        sh[t] = v;
        __syncthreads();
        for (int o = 1; o < 256; o <<= 1) {
            int x = (t >= o) ? sh[t - o] : 0;
            __syncthreads();
            sh[t] += x;
            __syncthreads();
        }
        if (t < nb) bsum[t] = sh[t] - v;   // exclusive
        __syncthreads();
    }
    if (t == 0) { g_offE[NEDGES] = NNZV; g_offV[NNODES] = NNZV; }
}

// ---------------- launch 4: local scan -> off/cur, fused coefficient compute ----------------
__global__ __launch_bounds__(256) void scan3c_kernel(const float* __restrict__ ew) {
    int w   = (blockIdx.x < NB_E) ? 0 : 1;
    int blk = w ? (blockIdx.x - NB_E) : blockIdx.x;
    int n   = w ? NNODES : NEDGES;
    const int* deg = w ? g_degV : g_degE;
    int* off  = w ? g_offV : g_offE;
    int* cur  = w ? g_curV : g_curE;
    const int* bsum = w ? g_bsumV : g_bsumE;

    int t = threadIdx.x;
    int base = blk * 1024 + t * 4;
    int a[4];
    int s = 0;
#pragma unroll
    for (int k = 0; k < 4; k++) {
        int i = base + k;
        a[k] = (i < n) ? deg[i] : 0;
        s += a[k];
    }
    __shared__ int sh[256];
    sh[t] = s;
    __syncthreads();
    for (int o = 1; o < 256; o <<= 1) {
        int x = (t >= o) ? sh[t - o] : 0;
        __syncthreads();
        sh[t] += x;
        __syncthreads();
    }
    int run = sh[t] - s + bsum[blk];
#pragma unroll
    for (int k = 0; k < 4; k++) {
        int i = base + k;
        if (i < n) {
            off[i] = run;
            cur[i] = run;
            run += a[k];
            if (w == 0) {
                // edge coefficients: c2 = ew/B, cb = ew (0 if empty)
                float B = (float)a[k];
                float wt = __ldg(&ew[i]);
                if (B > 0.f) { g_c2[i] = wt / B; g_cb[i] = wt; }
                else         { g_c2[i] = 0.f;   g_cb[i] = 0.f; }
            } else {
                float d = g_Dsum[i];
                g_Dinv[i] = (d > 0.f) ? (1.f / d) : 0.f;
            }
        }
    }
}

// ---------------- launch 5: fill both CSRs via cursor atomics ----------------
__global__ void fill_csr_kernel(const int* __restrict__ nidx,
                                const int* __restrict__ eidx) {
    int i = blockIdx.x * blockDim.x + threadIdx.x;
    if (i >= NNZV) return;
    int v = nidx[i];
    int e = eidx[i];
    int pe = atomicAdd(&g_curE[e], 1);
    g_csrE[pe] = v;
    int pv = atomicAdd(&g_curV[v], 1);
    g_csrV[pv] = e;
}

// ---------------- gather node -> edge (launch 6 = ncu profile target) ----------------
// 16 lanes per edge row, each lane owns one float4 column chunk.
// Software-pipelined by 4. src is either emb (layer 0) or g_z (relu already applied).
template <bool USE_Z>
__global__ __launch_bounds__(256) void gather_v2e_kernel(const float* __restrict__ x) {
    int t = blockIdx.x * 256 + threadIdx.x;
    int e = t >> 4;
    if (e >= NEDGES) return;
    int c = (t & 15) * 4;
    int start = __ldg(&g_offE[e]);
    int end   = __ldg(&g_offE[e + 1]);
    const float* src = USE_Z ? g_z : x;

    float4 acc = make_float4(0.f, 0.f, 0.f, 0.f);
    int j = start;
    for (; j + 3 < end; j += 4) {
        int v0 = __ldg(&g_csrE[j]);
        int v1 = __ldg(&g_csrE[j + 1]);
        int v2 = __ldg(&g_csrE[j + 2]);
        int v3 = __ldg(&g_csrE[j + 3]);
        float4 a = *reinterpret_cast<const float4*>(src + (size_t)v0 * HID + c);
        float4 b = *reinterpret_cast<const float4*>(src + (size_t)v1 * HID + c);
        float4 d = *reinterpret_cast<const float4*>(src + (size_t)v2 * HID + c);
        float4 f = *reinterpret_cast<const float4*>(src + (size_t)v3 * HID + c);
        acc.x += (a.x + b.x) + (d.x + f.x);
        acc.y += (a.y + b.y) + (d.y + f.y);
        acc.z += (a.z + b.z) + (d.z + f.z);
        acc.w += (a.w + b.w) + (d.w + f.w);
    }
    for (; j < end; j++) {
        int v0 = __ldg(&g_csrE[j]);
        float4 a = *reinterpret_cast<const float4*>(src + (size_t)v0 * HID + c);
        acc.x += a.x; acc.y += a.y; acc.z += a.z; acc.w += a.w;
    }
    *reinterpret_cast<float4*>(g_eraw + (size_t)e * HID + c) = acc;
}

// ---------------- gather edge -> node ----------------
// efeat already includes ew*Binv; sum, scale by Dinv.
// LAST=0: write relu(Dinv*acc) into g_z (relu folded into producer).
// LAST=1: write Dinv*acc into out.
template <int LAST>
__global__ __launch_bounds__(256) void gather_e2v_kernel(float* __restrict__ out) {
    int t = blockIdx.x * 256 + threadIdx.x;
    int v = t >> 4;
    if (v >= NNODES) return;
    int c = (t & 15) * 4;
    int start = __ldg(&g_offV[v]);
    int end   = __ldg(&g_offV[v + 1]);

    float4 acc = make_float4(0.f, 0.f, 0.f, 0.f);
    int j = start;
    for (; j + 3 < end; j += 4) {
        int e0 = __ldg(&g_csrV[j]);
        int e1 = __ldg(&g_csrV[j + 1]);
        int e2 = __ldg(&g_csrV[j + 2]);
        int e3 = __ldg(&g_csrV[j + 3]);
        float4 a = *reinterpret_cast<const float4*>(g_efeat + (size_t)e0 * HID + c);
        float4 b = *reinterpret_cast<const float4*>(g_efeat + (size_t)e1 * HID + c);
        float4 d = *reinterpret_cast<const float4*>(g_efeat + (size_t)e2 * HID + c);
        float4 f = *reinterpret_cast<const float4*>(g_efeat + (size_t)e3 * HID + c);
        acc.x += (a.x + b.x) + (d.x + f.x);
        acc.y += (a.y + b.y) + (d.y + f.y);
        acc.z += (a.z + b.z) + (d.z + f.z);
        acc.w += (a.w + b.w) + (d.w + f.w);
    }
    for (; j < end; j++) {
        int e0 = __ldg(&g_csrV[j]);
        float4 a = *reinterpret_cast<const float4*>(g_efeat + (size_t)e0 * HID + c);
        acc.x += a.x; acc.y += a.y; acc.z += a.z; acc.w += a.w;
    }
    float s = __ldg(&g_Dinv[v]);
    acc.x *= s; acc.y *= s; acc.z *= s; acc.w *= s;
    if (LAST == 0) {
        acc.x = fmaxf(acc.x, 0.f); acc.y = fmaxf(acc.y, 0.f);
        acc.z = fmaxf(acc.z, 0.f); acc.w = fmaxf(acc.w, 0.f);
        *reinterpret_cast<float4*>(g_z + (size_t)v * HID + c) = acc;
    } else {
        *reinterpret_cast<float4*>(out + (size_t)v * HID + c) = acc;
    }
}

// ---------------- edge GEMM: efeat[e,:] = c2[e]*(eraw[e,:] @ W^T) + cb[e]*b ----------------
__global__ __launch_bounds__(256) void edge_gemm_kernel(const float* __restrict__ W,
                                                        const float* __restrict__ b) {
    __shared__ float WsT[HID][HID];  // WsT[k][j] = W[j,k]
    __shared__ float bs[HID];

    int tid = threadIdx.x;
    for (int idx = tid; idx < HID * HID; idx += 256) {
        int j = idx & (HID - 1);
        int k = idx >> 6;
        WsT[k][j] = W[j * HID + k];
    }
    if (tid < HID) bs[tid] = b[tid];
    __syncthreads();

    int rp = tid >> 2;
    int cq = tid & 3;
    int r0 = blockIdx.x * 128 + rp * 2;
    int r1 = r0 + 1;
    bool ok0 = (r0 < NEDGES);
    bool ok1 = (r1 < NEDGES);

    float4 a0[4], a1[4];
#pragma unroll
    for (int jq = 0; jq < 4; jq++) {
        a0[jq] = make_float4(0.f, 0.f, 0.f, 0.f);
        a1[jq] = make_float4(0.f, 0.f, 0.f, 0.f);
    }

    const float4* x0p = reinterpret_cast<const float4*>(g_eraw + (size_t)(ok0 ? r0 : 0) * HID);
    const float4* x1p = reinterpret_cast<const float4*>(g_eraw + (size_t)(ok1 ? r1 : 0) * HID);

#pragma unroll 4
    for (int k4 = 0; k4 < HID / 4; k4++) {
        float4 xa = ok0 ? __ldg(&x0p[k4]) : make_float4(0.f, 0.f, 0.f, 0.f);
        float4 xb = ok1 ? __ldg(&x1p[k4]) : make_float4(0.f, 0.f, 0.f, 0.f);
        float xav[4] = {xa.x, xa.y, xa.z, xa.w};
        float xbv[4] = {xb.x, xb.y, xb.z, xb.w};
#pragma unroll
        for (int kk = 0; kk < 4; kk++) {
            int k = k4 * 4 + kk;
#pragma unroll
            for (int jq = 0; jq < 4; jq++) {
                float4 w = *reinterpret_cast<const float4*>(&WsT[k][cq * 4 + jq * 16]);
                a0[jq].x = fmaf(xav[kk], w.x, a0[jq].x);
                a0[jq].y = fmaf(xav[kk], w.y, a0[jq].y);
                a0[jq].z = fmaf(xav[kk], w.z, a0[jq].z);
                a0[jq].w = fmaf(xav[kk], w.w, a0[jq].w);
                a1[jq].x = fmaf(xbv[kk], w.x, a1[jq].x);
                a1[jq].y = fmaf(xbv[kk], w.y, a1[jq].y);
                a1[jq].z = fmaf(xbv[kk], w.z, a1[jq].z);
                a1[jq].w = fmaf(xbv[kk], w.w, a1[jq].w);
            }
        }
    }

    if (ok0) {
        float c2 = g_c2[r0];
        float cb = g_cb[r0];
#pragma unroll
        for (int jq = 0; jq < 4; jq++) {
            int jb = jq * 16 + cq * 4;
            float4 r;
            r.x = fmaf(cb, bs[jb + 0], c2 * a0[jq].x);
            r.y = fmaf(cb, bs[jb + 1], c2 * a0[jq].y);
            r.z = fmaf(cb, bs[jb + 2], c2 * a0[jq].z);
            r.w = fmaf(cb, bs[jb + 3], c2 * a0[jq].w);
            *reinterpret_cast<float4*>(g_efeat + (size_t)r0 * HID + jb) = r;
        }
    }
    if (ok1) {
        float c2 = g_c2[r1];
        float cb = g_cb[r1];
#pragma unroll
        for (int jq = 0; jq < 4; jq++) {
            int jb = jq * 16 + cq * 4;
            float4 r;
            r.x = fmaf(cb, bs[jb + 0], c2 * a1[jq].x);
            r.y = fmaf(cb, bs[jb + 1], c2 * a1[jq].y);
            r.z = fmaf(cb, bs[jb + 2], c2 * a1[jq].z);
            r.w = fmaf(cb, bs[jb + 3], c2 * a1[jq].w);
            *reinterpret_cast<float4*>(g_efeat + (size_t)r1 * HID + jb) = r;
        }
    }
}

// ---------------- trailing cleanup: restore zeroed-counter invariant for next replay ----------------
__global__ void cleanup_kernel() {
    int i = blockIdx.x * blockDim.x + threadIdx.x;
    if (i < NNODES) { g_Dsum[i] = 0.f; g_degV[i] = 0; }
    if (i < NEDGES) { g_degE[i] = 0; }
}

// ---------------- launch ----------------
extern "C" void kernel_launch(void* const* d_in, const int* in_sizes, int n_in,
                              void* d_out, int out_size) {
    const int*   hidx = (const int*)d_in[0];
    const int*   nidx = hidx;             // hyperedge_index[0] = node idx
    const int*   eidx = hidx + NNZV;      // hyperedge_index[1] = edge idx
    const float* ew   = (const float*)d_in[1];
    const float* emb  = (const float*)d_in[2];
    const float* Wm[3] = {(const float*)d_in[3], (const float*)d_in[5], (const float*)d_in[7]};
    const float* bm[3] = {(const float*)d_in[4], (const float*)d_in[6], (const float*)d_in[8]};
    float* out = (float*)d_out;

    const int T = 256;

    // preprocessing: exactly 5 launches (deg arrays pre-zeroed: static init on first
    // call, trailing cleanup_kernel on every subsequent call/replay)
    deg_count_kernel<<<(NNZV + T - 1) / T, T>>>(nidx, eidx, ew);
    scan1c_kernel<<<NB_E + NB_V, T>>>();
    scan2c_kernel<<<1, T>>>();
    scan3c_kernel<<<NB_E + NB_V, T>>>(ew);
    fill_csr_kernel<<<(NNZV + T - 1) / T, T>>>(nidx, eidx);

    const int V2E_BLOCKS  = (NEDGES * 16) / T;   // 6250
    const int E2V_BLOCKS  = (NNODES * 16) / T;   // 12500
    const int GEMM_BLOCKS = (NEDGES + 127) / 128;

    for (int l = 0; l < 3; l++) {
        if (l == 0)
            gather_v2e_kernel<false><<<V2E_BLOCKS, T>>>(emb);   // launch #6: ncu target
        else
            gather_v2e_kernel<true><<<V2E_BLOCKS, T>>>(nullptr);
        edge_gemm_kernel<<<GEMM_BLOCKS, T>>>(Wm[l], bm[l]);
        if (l < 2)
            gather_e2v_kernel<0><<<E2V_BLOCKS, T>>>(nullptr);
        else
            gather_e2v_kernel<1><<<E2V_BLOCKS, T>>>(out);
    }

    cleanup_kernel<<<(NNODES + T - 1) / T, T>>>();
}